// round 3
// baseline (speedup 1.0000x reference)
#include <cuda_runtime.h>

#define N_NODES 50000
#define N_EDGES 640000
#define D 128

#define EPW 8   // edges per warp (edge kernel)
#define NPW 8   // nodes per warp (node kernel)

// Scratch for per-node projections (no cudaMalloc allowed).
__device__ float g_a[N_NODES];   // h[n] . w_src
__device__ float g_b[N_NODES];   // h[n] . w_dst

// One warp handles NPW nodes: a[n] = h[n].w_src, b[n] = h[n].w_dst
__global__ __launch_bounds__(256) void node_proj_kernel(
        const float* __restrict__ h,
        const float* __restrict__ weight) {
    int gwarp = (blockIdx.x * blockDim.x + threadIdx.x) >> 5;
    int lane  = threadIdx.x & 31;
    int base  = gwarp * NPW;
    if (base < N_NODES) {
        const float4* w4 = reinterpret_cast<const float4*>(weight);
        float4 ws = __ldg(w4 + lane);        // weight[0,   0:128)
        float4 wd = __ldg(w4 + 32 + lane);   // weight[0, 128:256)

        const float4* h4 = reinterpret_cast<const float4*>(h);

        // Issue all loads first (MLP), guarded for tail.
        float4 hv[NPW];
        #pragma unroll
        for (int k = 0; k < NPW; k++) {
            int n = base + k;
            hv[k] = (n < N_NODES) ? __ldcs(h4 + (size_t)n * 32 + lane)
                                  : make_float4(0.f, 0.f, 0.f, 0.f);
        }

        float pa[NPW], pb[NPW];
        #pragma unroll
        for (int k = 0; k < NPW; k++) {
            pa[k] = hv[k].x * ws.x + hv[k].y * ws.y + hv[k].z * ws.z + hv[k].w * ws.w;
            pb[k] = hv[k].x * wd.x + hv[k].y * wd.y + hv[k].z * wd.z + hv[k].w * wd.w;
        }

        #pragma unroll
        for (int off = 16; off >= 1; off >>= 1) {
            #pragma unroll
            for (int k = 0; k < NPW; k++) {
                pa[k] += __shfl_xor_sync(0xFFFFFFFFu, pa[k], off);
                pb[k] += __shfl_xor_sync(0xFFFFFFFFu, pb[k], off);
            }
        }

        if (lane < NPW && base + lane < N_NODES) {
            float va = pa[0], vb = pb[0];
            #pragma unroll
            for (int k = 1; k < NPW; k++) {
                if (lane == k) { va = pa[k]; vb = pb[k]; }
            }
            g_a[base + lane] = va;
            g_b[base + lane] = vb;
        }
    }

    // Allow the dependent edge kernel to be scheduled as early as possible.
    cudaTriggerProgrammaticLaunchCompletion();
}

// One warp handles EPW edges: out[i] = a[src[i]] + b[dst[i]] + e[i].w_e + bias
// Launched with PDL: everything before cudaGridDependencySynchronize() is
// independent of the node kernel and overlaps with it.
__global__ __launch_bounds__(256) void edge_kernel(
        const float* __restrict__ e,
        const int*   __restrict__ src,
        const int*   __restrict__ dst,
        const float* __restrict__ weight,
        const float* __restrict__ bias,
        float*       __restrict__ out) {
    int gwarp = (blockIdx.x * blockDim.x + threadIdx.x) >> 5;
    int lane  = threadIdx.x & 31;
    int base  = gwarp * EPW;
    if (base >= N_EDGES) {
        cudaGridDependencySynchronize();
        return;
    }

    const float4* w4 = reinterpret_cast<const float4*>(weight);
    float4 we = __ldg(w4 + 64 + lane);   // weight[0, 256:384)

    const float4* e4 = reinterpret_cast<const float4*>(e);

    // Issue all EPW streaming loads up front -> high MLP.
    float4 ev[EPW];
    #pragma unroll
    for (int k = 0; k < EPW; k++) {
        ev[k] = __ldcs(e4 + (size_t)(base + k) * 32 + lane);
    }

    // Hoist index loads (independent of node kernel output).
    int s = 0, d = 0;
    if (lane < EPW) {
        s = src[base + lane];
        d = dst[base + lane];
    }
    float bv = __ldg(bias);

    float p[EPW];
    #pragma unroll
    for (int k = 0; k < EPW; k++) {
        p[k] = ev[k].x * we.x + ev[k].y * we.y + ev[k].z * we.z + ev[k].w * we.w;
    }

    #pragma unroll
    for (int off = 16; off >= 1; off >>= 1) {
        #pragma unroll
        for (int k = 0; k < EPW; k++) {
            p[k] += __shfl_xor_sync(0xFFFFFFFFu, p[k], off);
        }
    }

    // Wait for node projections to be globally visible.
    cudaGridDependencySynchronize();

    // Lanes 0..EPW-1 each finalize one edge (parallel L2 gathers + stores).
    if (lane < EPW) {
        float pe = p[0];
        #pragma unroll
        for (int k = 1; k < EPW; k++) {
            if (lane == k) pe = p[k];
        }
        out[base + lane] = pe + g_a[s] + g_b[d] + bv;
    }
}

extern "C" void kernel_launch(void* const* d_in, const int* in_sizes, int n_in,
                              void* d_out, int out_size) {
    const float* h      = (const float*)d_in[0];
    const float* e      = (const float*)d_in[1];
    const int*   src    = (const int*)d_in[2];
    const int*   dst    = (const int*)d_in[3];
    const float* weight = (const float*)d_in[4];
    const float* bias   = (const float*)d_in[5];
    float*       out    = (float*)d_out;

    // Node kernel: 50000 nodes / 8 per warp = 6250 warps; 8 warps/block.
    {
        int warps  = (N_NODES + NPW - 1) / NPW;
        int blocks = (warps + 7) / 8;
        node_proj_kernel<<<blocks, 256>>>(h, weight);
    }

    // Edge kernel: launched with Programmatic Dependent Launch so its
    // e-streaming phase overlaps the node kernel.
    {
        int warps  = (N_EDGES + EPW - 1) / EPW;
        int blocks = (warps + 7) / 8;

        cudaLaunchConfig_t cfg = {};
        cfg.gridDim  = dim3(blocks, 1, 1);
        cfg.blockDim = dim3(256, 1, 1);
        cfg.dynamicSmemBytes = 0;
        cfg.stream = 0;

        cudaLaunchAttribute attrs[1];
        attrs[0].id = cudaLaunchAttributeProgrammaticStreamSerialization;
        attrs[0].val.programmaticStreamSerializationAllowed = 1;
        cfg.attrs = attrs;
        cfg.numAttrs = 1;

        cudaLaunchKernelEx(&cfg, edge_kernel, e, src, dst, weight, bias, out);
    }
}